// round 15
// baseline (speedup 1.0000x reference)
#include <cuda_runtime.h>
#include <cuda_bf16.h>
#include <mma.h>
#include <cstdint>

using namespace nvcuda;

#define Bm 512
#define Em 256
#define Am 128
#define Km 6
#define Fm 147
#define AFm 133
#define Hm 128

#define KWI 160
#define KWO 288          // 133 af + 11 zero + 128 m2a + 16 zero (9 chunks of 32)
#define LDA_WI 168
#define LDT 40           // fused-kernel A/B tile stride (bf16, mult of 8)

// f32 scratch
__device__ float g_inp [Bm * Em * Hm];
__device__ float g_msgA[Bm * Em * Hm];
__device__ int   g_off[Bm];
// pre-split hi/lo bf16 weights, row-major [128][K]
__device__ __align__(16) __nv_bfloat16 g_WiH[128 * KWI];
__device__ __align__(16) __nv_bfloat16 g_WiL[128 * KWI];
__device__ __align__(16) __nv_bfloat16 g_WhH[128 * 128];
__device__ __align__(16) __nv_bfloat16 g_WhL[128 * 128];
__device__ __align__(16) __nv_bfloat16 g_WoH[128 * KWO];
__device__ __align__(16) __nv_bfloat16 g_WoL[128 * KWO];

typedef wmma::fragment<wmma::matrix_a, 16, 16, 16, __nv_bfloat16, wmma::row_major> FragA;
typedef wmma::fragment<wmma::matrix_b, 16, 16, 16, __nv_bfloat16, wmma::col_major> FragB;
typedef wmma::fragment<wmma::accumulator, 16, 16, 16, float> FragC;

// single shared symbol for all kernels
extern __shared__ char smdyn[];

__device__ __forceinline__ uint32_t packhl(float x) {
    __nv_bfloat16 h = __float2bfloat16_rn(x);
    __nv_bfloat16 l = __float2bfloat16_rn(x - __bfloat162float(h));
    return (uint32_t)__bfloat16_as_ushort(h) | ((uint32_t)__bfloat16_as_ushort(l) << 16);
}
__device__ __forceinline__ float unphl(uint32_t w) {
    return __bfloat162float(__ushort_as_bfloat16((unsigned short)(w & 0xffffu)))
         + __bfloat162float(__ushort_as_bfloat16((unsigned short)(w >> 16)));
}
// pack 4 floats into hi-uint2 / lo-uint2
__device__ __forceinline__ void pack4(const float* v, uint2& hp, uint2& lp) {
    __nv_bfloat16 h0 = __float2bfloat16_rn(v[0]), h1 = __float2bfloat16_rn(v[1]),
                  h2 = __float2bfloat16_rn(v[2]), h3 = __float2bfloat16_rn(v[3]);
    hp.x = (uint32_t)__bfloat16_as_ushort(h0) | ((uint32_t)__bfloat16_as_ushort(h1) << 16);
    hp.y = (uint32_t)__bfloat16_as_ushort(h2) | ((uint32_t)__bfloat16_as_ushort(h3) << 16);
    __nv_bfloat16 l0 = __float2bfloat16_rn(v[0] - __bfloat162float(h0));
    __nv_bfloat16 l1 = __float2bfloat16_rn(v[1] - __bfloat162float(h1));
    __nv_bfloat16 l2 = __float2bfloat16_rn(v[2] - __bfloat162float(h2));
    __nv_bfloat16 l3 = __float2bfloat16_rn(v[3] - __bfloat162float(h3));
    lp.x = (uint32_t)__bfloat16_as_ushort(l0) | ((uint32_t)__bfloat16_as_ushort(l1) << 16);
    lp.y = (uint32_t)__bfloat16_as_ushort(l2) | ((uint32_t)__bfloat16_as_ushort(l3) << 16);
}
__device__ __forceinline__ void wr4(__nv_bfloat16* AH, __nv_bfloat16* AL,
                                    int ldm, int r, int c, float4 v) {
    int o = r * ldm + c;
    float vv[4] = {v.x, v.y, v.z, v.w};
    uint2 hp, lp;
    pack4(vv, hp, lp);
    *(uint2*)(AH + o) = hp;
    *(uint2*)(AL + o) = lp;
}

// ---------------------------------------------------------------------------
extern "C" __global__ void __launch_bounds__(512) k_scan(const int* __restrict__ ml,
                                                         float* __restrict__ maskbase)
{
    __shared__ int s[512];
    int t = threadIdx.x;
    int v = ml[t];
    s[t] = v;
    __syncthreads();
    for (int off = 1; off < 512; off <<= 1) {
        int u = (t >= off) ? s[t - off] : 0;
        __syncthreads();
        s[t] += u;
        __syncthreads();
    }
    g_off[t] = s[t] - v;
    for (int i = t; i < Bm * Am; i += 512) {
        int b = i >> 7, a = i & 127;
        maskbase[i] = (a < ml[b]) ? 1.0f : 0.0f;
    }
}

// ---------------------------------------------------------------------------
extern "C" __global__ void __launch_bounds__(256) k_tw(const float* __restrict__ Wi,
                                                       const float* __restrict__ Wh,
                                                       const float* __restrict__ Wo)
{
    int idx = blockIdx.x * 256 + threadIdx.x;
    float v; __nv_bfloat16 *ph, *pl; int o;
    if (idx < 128 * KWI) {
        int n = idx / KWI, k = idx - n * KWI;
        v = (k < Fm) ? Wi[n * Fm + k] : 0.f;
        ph = g_WiH; pl = g_WiL; o = idx;
    } else if (idx < 128 * KWI + 128 * 128) {
        int p = idx - 128 * KWI;
        v = Wh[p];
        ph = g_WhH; pl = g_WhL; o = p;
    } else if (idx < 128 * (KWI + 128 + KWO)) {
        int p = idx - 128 * KWI - 128 * 128;
        int n = p / KWO, k = p - n * KWO;
        if (k < AFm)                     v = Wo[n * 261 + k];
        else if (k >= 144 && k < 272)    v = Wo[n * 261 + k - 11];
        else                             v = 0.f;
        ph = g_WoH; pl = g_WoL; o = p;
    } else return;
    __nv_bfloat16 h = __float2bfloat16_rn(v);
    ph[o] = h;
    pl[o] = __float2bfloat16_rn(v - __bfloat162float(h));
}

// ---------------------------------------------------------------------------
// k_wi (R8-proven): inp = fin @ Wi^T ; msgA = relu(inp).  grid 1024, 1D warp tile.
// ---------------------------------------------------------------------------
#define WI_AH 0
#define WI_AL (128 * LDA_WI)
#define WI_BH (2 * 128 * LDA_WI)
#define WI_BL (3 * 128 * LDA_WI)
#define WI_SMB (4 * 128 * LDA_WI * 2)
#define LD_128 136

extern "C" __global__ void __launch_bounds__(256) k_wi(const float* __restrict__ fin)
{
    __nv_bfloat16* sm = (__nv_bfloat16*)smdyn;
    int tid = threadIdx.x, w = tid >> 5;
    int row0 = blockIdx.x * 128;

    {
        const uint4* sh = (const uint4*)g_WiH;
        const uint4* sl = (const uint4*)g_WiL;
        for (int i = tid; i < 128 * KWI / 8; i += 256) {
            int r = i / (KWI / 8), ch = i - r * (KWI / 8);
            *(uint4*)(sm + WI_BH + r * LDA_WI + ch * 8) = sh[i];
            *(uint4*)(sm + WI_BL + r * LDA_WI + ch * 8) = sl[i];
        }
    }
    {
        int r = tid >> 1, h = tid & 1;
        const float* fr = fin + (size_t)(row0 + r) * Fm;
        for (int c = h * 80; c < h * 80 + 80; c += 4) {
            float4 v;
            v.x = (c + 0 < Fm) ? fr[c + 0] : 0.f;
            v.y = (c + 1 < Fm) ? fr[c + 1] : 0.f;
            v.z = (c + 2 < Fm) ? fr[c + 2] : 0.f;
            v.w = (c + 3 < Fm) ? fr[c + 3] : 0.f;
            wr4(sm + WI_AH, sm + WI_AL, LDA_WI, r, c, v);
        }
    }
    __syncthreads();

    FragC c[8];
#pragma unroll
    for (int nt = 0; nt < 8; nt++) wmma::fill_fragment(c[nt], 0.f);
    for (int ks = 0; ks < KWI / 16; ks++) {
        FragA ah, al;
        wmma::load_matrix_sync(ah, sm + WI_AH + w * 16 * LDA_WI + ks * 16, LDA_WI);
        wmma::load_matrix_sync(al, sm + WI_AL + w * 16 * LDA_WI + ks * 16, LDA_WI);
#pragma unroll
        for (int nt = 0; nt < 8; nt++) {
            FragB bh, bl;
            wmma::load_matrix_sync(bh, sm + WI_BH + nt * 16 * LDA_WI + ks * 16, LDA_WI);
            wmma::load_matrix_sync(bl, sm + WI_BL + nt * 16 * LDA_WI + ks * 16, LDA_WI);
            wmma::mma_sync(c[nt], ah, bh, c[nt]);
            wmma::mma_sync(c[nt], ah, bl, c[nt]);
            wmma::mma_sync(c[nt], al, bh, c[nt]);
        }
    }
    __syncthreads();

    float* Cs = (float*)smdyn;
#pragma unroll
    for (int nt = 0; nt < 8; nt++)
        wmma::store_matrix_sync(Cs + w * 16 * LD_128 + nt * 16, c[nt], LD_128, wmma::mem_row_major);
    __syncthreads();

    {
        int r = tid >> 1, hb = (tid & 1) * 64;
        const float* cr = Cs + r * LD_128 + hb;
        size_t base = (size_t)(row0 + r) * Hm + hb;
        float4* pi = (float4*)(g_inp + base);
        float4* pm = (float4*)(g_msgA + base);
#pragma unroll
        for (int q = 0; q < 16; q++) {
            float x0 = cr[4 * q], x1 = cr[4 * q + 1], x2 = cr[4 * q + 2], x3 = cr[4 * q + 3];
            pi[q] = make_float4(x0, x1, x2, x3);
            pm[q] = make_float4(fmaxf(x0, 0.f), fmaxf(x1, 0.f), fmaxf(x2, 0.f), fmaxf(x3, 0.f));
        }
    }
}

// ---------------------------------------------------------------------------
// k_fuse: per-molecule block. msg lives in smem (packed hi/lo uint32, pair-XOR
// swizzle). 2x message-passing iterations + output GEMM + scatter, fused.
// msg pair layout: pair(r, p) at msgP[r*64 + (p ^ (r&15))], pair p = cols 2p,2p+1
// ---------------------------------------------------------------------------
#define F_MSG 0
#define F_AH  131072
#define F_AL  (F_AH + 256 * LDT * 2)      // 151552
#define F_BH  (F_AL + 256 * LDT * 2)      // 172032
#define F_BL  (F_BH + 128 * LDT * 2)      // 182272
#define F_BIAS (F_BL + 128 * LDT * 2)     // 192512
#define F_SMB (F_BIAS + 512)              // 193024

extern "C" __global__ void __launch_bounds__(256, 1) k_fuse(const int* __restrict__ mapping,
                                                            const int* __restrict__ a2b,
                                                            const float* __restrict__ af,
                                                            const float* __restrict__ bo,
                                                            const int* __restrict__ ml,
                                                            float* __restrict__ out)
{
    uint2*  msgP = (uint2*)(smdyn + F_MSG);            // 64 pairs per row
    float*  msgF = (float*)(smdyn + F_MSG);            // f32 scratch alias
    __nv_bfloat16* AHp = (__nv_bfloat16*)(smdyn + F_AH);
    __nv_bfloat16* ALp = (__nv_bfloat16*)(smdyn + F_AL);
    __nv_bfloat16* BHp = (__nv_bfloat16*)(smdyn + F_BH);
    __nv_bfloat16* BLp = (__nv_bfloat16*)(smdyn + F_BL);
    float* biasF = (float*)(smdyn + F_BIAS);

    int tid = threadIdx.x, w = tid >> 5;
    int b = blockIdx.x;

    if (tid < 128) biasF[tid] = bo[tid];

    // per-thread bond mapping (row = tid)
    int map6[6];
    {
        const int* mp = mapping + ((size_t)b * Em + tid) * Km;
#pragma unroll
        for (int s = 0; s < 6; s++) map6[s] = mp[s];
    }

    // ---- load msgA -> packed swizzled smem ----
    {
        const float4* src = (const float4*)(g_msgA + (size_t)b * Em * Hm);
        for (int i = tid; i < Em * 32; i += 256) {      // 32 float4 per row
            int r = i >> 5, ch = i & 31;
            float4 v = src[(size_t)r * 32 + ch];
            float vv[4] = {v.x, v.y, v.z, v.w};
            uint2 hp, lp;
            pack4(vv, hp, lp);
            uint2 w0, w1;
            w0.x = (hp.x & 0xffffu) | (lp.x << 16);                  // elem 0
            w0.y = (hp.x >> 16) | (lp.x & 0xffff0000u);              // elem 1
            w1.x = (hp.y & 0xffffu) | (lp.y << 16);                  // elem 2
            w1.y = (hp.y >> 16) | (lp.y & 0xffff0000u);              // elem 3
            int x = r & 15;
            msgP[r * 64 + ((2 * ch) ^ x)]     = w0;
            msgP[r * 64 + ((2 * ch + 1) ^ x)] = w1;
        }
    }

    // ================= message-passing iterations =================
    for (int iter = 0; iter < 2; iter++) {
        FragC c[2][8];
#pragma unroll
        for (int mt = 0; mt < 2; mt++)
#pragma unroll
            for (int nt = 0; nt < 8; nt++) wmma::fill_fragment(c[mt][nt], 0.f);

        for (int kc = 0; kc < 4; kc++) {
            __syncthreads();   // prev MMA (or init pack) done before overwrite
            // stage Wh chunk [128][32] hi/lo
            {
                int n = tid >> 1, hf = tid & 1;
                const uint4* sh = (const uint4*)(g_WhH + n * 128 + kc * 32 + hf * 16);
                const uint4* sl = (const uint4*)(g_WhL + n * 128 + kc * 32 + hf * 16);
                uint4* dh = (uint4*)(BHp + n * LDT + hf * 16);
                uint4* dl = (uint4*)(BLp + n * LDT + hf * 16);
                dh[0] = sh[0]; dh[1] = sh[1];
                dl[0] = sl[0]; dl[1] = sl[1];
            }
            // build A chunk: row = tid, cols kc*32..+32 (gather-sum 6 from msg)
            {
                int r = tid;
#pragma unroll
                for (int g = 0; g < 4; g++) {           // 8 cols per group
                    float acc[8] = {0.f, 0.f, 0.f, 0.f, 0.f, 0.f, 0.f, 0.f};
                    int pbase = kc * 16 + g * 4;
#pragma unroll
                    for (int s = 0; s < 6; s++) {
                        const uint2* mrow = msgP + map6[s] * 64;
                        int x = map6[s] & 15;
#pragma unroll
                        for (int q = 0; q < 4; q++) {
                            uint2 wv = mrow[(pbase + q) ^ x];
                            acc[2 * q]     += unphl(wv.x);
                            acc[2 * q + 1] += unphl(wv.y);
                        }
                    }
                    uint2 h0, l0, h1, l1;
                    pack4(acc, h0, l0);
                    pack4(acc + 4, h1, l1);
                    *(uint4*)(AHp + r * LDT + g * 8) = make_uint4(h0.x, h0.y, h1.x, h1.y);
                    *(uint4*)(ALp + r * LDT + g * 8) = make_uint4(l0.x, l0.y, l1.x, l1.y);
                }
            }
            __syncthreads();
            // MMA: warp rows [w*32, +32), N=128
#pragma unroll
            for (int ki = 0; ki < 2; ki++) {
                FragA ah[2], al[2];
#pragma unroll
                for (int mt = 0; mt < 2; mt++) {
                    wmma::load_matrix_sync(ah[mt], AHp + (w * 32 + mt * 16) * LDT + ki * 16, LDT);
                    wmma::load_matrix_sync(al[mt], ALp + (w * 32 + mt * 16) * LDT + ki * 16, LDT);
                }
#pragma unroll
                for (int nt = 0; nt < 8; nt++) {
                    FragB bh, bl;
                    wmma::load_matrix_sync(bh, BHp + nt * 16 * LDT + ki * 16, LDT);
                    wmma::load_matrix_sync(bl, BLp + nt * 16 * LDT + ki * 16, LDT);
#pragma unroll
                    for (int mt = 0; mt < 2; mt++) {
                        wmma::mma_sync(c[mt][nt], ah[mt], bh, c[mt][nt]);
                        wmma::mma_sync(c[mt][nt], ah[mt], bl, c[mt][nt]);
                        wmma::mma_sync(c[mt][nt], al[mt], bh, c[mt][nt]);
                    }
                }
            }
        }
        // epilogue: msg = relu(inp + C)
        __syncthreads();     // all gathers + MMA done
#pragma unroll
        for (int mt = 0; mt < 2; mt++)
#pragma unroll
            for (int nt = 0; nt < 8; nt++)
                wmma::store_matrix_sync(msgF + (w * 32 + mt * 16) * 128 + nt * 16,
                                        c[mt][nt], 128, wmma::mem_row_major);
        __syncthreads();
        {
            int r = tid, x = r & 15;
            const float4* gi = (const float4*)(g_inp + ((size_t)b * Em + r) * 128);
            float* mf = msgF + r * 128;
#pragma unroll
            for (int g = 0; g < 4; g++) {      // group of 32 cols = 16 pairs (swizzle-closed)
                float v[32];
#pragma unroll
                for (int q = 0; q < 8; q++) {
                    float4 cv = *(const float4*)(mf + g * 32 + q * 4);
                    float4 iv = gi[g * 8 + q];
                    v[4 * q]     = fmaxf(cv.x + iv.x, 0.f);
                    v[4 * q + 1] = fmaxf(cv.y + iv.y, 0.f);
                    v[4 * q + 2] = fmaxf(cv.z + iv.z, 0.f);
                    v[4 * q + 3] = fmaxf(cv.w + iv.w, 0.f);
                }
                uint2 w2[16];
#pragma unroll
                for (int q = 0; q < 16; q++) {
                    w2[q].x = packhl(v[2 * q]);
                    w2[q].y = packhl(v[2 * q + 1]);
                }
#pragma unroll
                for (int q = 0; q < 16; q++) {
                    int p = g * 16 + q;
                    msgP[r * 64 + (p ^ x)] = w2[q];
                }
            }
        }
    }

    // ================= output GEMM (atoms) =================
    int a = tid >> 1, half = tid & 1;
    int g6[6];
    {
        const int* gp = a2b + ((size_t)b * Am + a) * Km;
#pragma unroll
        for (int s = 0; s < 6; s++) g6[s] = gp[s];
    }

    FragC co[8];
#pragma unroll
    for (int nt = 0; nt < 8; nt++) wmma::fill_fragment(co[nt], 0.f);

    const float* afrow = af + ((size_t)b * Am + a) * AFm;
    for (int kc = 0; kc < 9; kc++) {
        __syncthreads();
        // stage Wo chunk
        {
            int n = tid >> 1, hf = tid & 1;
            const uint4* sh = (const uint4*)(g_WoH + n * KWO + kc * 32 + hf * 16);
            const uint4* sl = (const uint4*)(g_WoL + n * KWO + kc * 32 + hf * 16);
            uint4* dh = (uint4*)(BHp + n * LDT + hf * 16);
            uint4* dl = (uint4*)(BLp + n * LDT + hf * 16);
            dh[0] = sh[0]; dh[1] = sh[1];
            dl[0] = sl[0]; dl[1] = sl[1];
        }
        // build A-cat chunk rows 0..127 (2 threads/row, 16 cols each)
        {
            int k0 = kc * 32 + half * 16;
            float vv[16];
            if (k0 + 16 <= AFm) {
#pragma unroll
                for (int j = 0; j < 16; j++) vv[j] = afrow[k0 + j];
            } else if (k0 == 128) {
#pragma unroll
                for (int j = 0; j < 16; j++) vv[j] = (128 + j < AFm) ? afrow[128 + j] : 0.f;
            } else if (k0 >= 144 && k0 < 272) {
#pragma unroll
                for (int j = 0; j < 16; j++) vv[j] = 0.f;
                int p0 = (k0 - 144) >> 1;
#pragma unroll
                for (int s = 0; s < 6; s++) {
                    const uint2* mrow = msgP + g6[s] * 64;
                    int x = g6[s] & 15;
#pragma unroll
                    for (int q = 0; q < 8; q++) {
                        uint2 wv = mrow[(p0 + q) ^ x];
                        vv[2 * q]     += unphl(wv.x);
                        vv[2 * q + 1] += unphl(wv.y);
                    }
                }
            } else {
#pragma unroll
                for (int j = 0; j < 16; j++) vv[j] = 0.f;
            }
            uint2 h0, l0, h1, l1, h2, l2, h3, l3;
            pack4(vv, h0, l0); pack4(vv + 4, h1, l1);
            pack4(vv + 8, h2, l2); pack4(vv + 12, h3, l3);
            uint4* dh = (uint4*)(AHp + a * LDT + half * 16);
            uint4* dl = (uint4*)(ALp + a * LDT + half * 16);
            dh[0] = make_uint4(h0.x, h0.y, h1.x, h1.y);
            dh[1] = make_uint4(h2.x, h2.y, h3.x, h3.y);
            dl[0] = make_uint4(l0.x, l0.y, l1.x, l1.y);
            dl[1] = make_uint4(l2.x, l2.y, l3.x, l3.y);
        }
        __syncthreads();
        // MMA: warp rows [w*16, +16)
#pragma unroll
        for (int ki = 0; ki < 2; ki++) {
            FragA ah, al;
            wmma::load_matrix_sync(ah, AHp + w * 16 * LDT + ki * 16, LDT);
            wmma::load_matrix_sync(al, ALp + w * 16 * LDT + ki * 16, LDT);
#pragma unroll
            for (int nt = 0; nt < 8; nt++) {
                FragB bh, bl;
                wmma::load_matrix_sync(bh, BHp + nt * 16 * LDT + ki * 16, LDT);
                wmma::load_matrix_sync(bl, BLp + nt * 16 * LDT + ki * 16, LDT);
                wmma::mma_sync(co[nt], ah, bh, co[nt]);
                wmma::mma_sync(co[nt], ah, bl, co[nt]);
                wmma::mma_sync(co[nt], al, bh, co[nt]);
            }
        }
    }
    __syncthreads();
#pragma unroll
    for (int nt = 0; nt < 8; nt++)
        wmma::store_matrix_sync(msgF + w * 16 * 128 + nt * 16, co[nt], 128, wmma::mem_row_major);
    __syncthreads();

    // bias + relu + scatter (2 threads/row)
    {
        int len = ml[b];
        if (a < len) {
            const float* cr = msgF + a * 128 + half * 64;
            const float* bs = biasF + half * 64;
            float4* po = (float4*)(out + (size_t)(g_off[b] + a) * Hm + half * 64);
#pragma unroll
            for (int q = 0; q < 16; q++)
                po[q] = make_float4(fmaxf(cr[4 * q + 0] + bs[4 * q + 0], 0.f),
                                    fmaxf(cr[4 * q + 1] + bs[4 * q + 1], 0.f),
                                    fmaxf(cr[4 * q + 2] + bs[4 * q + 2], 0.f),
                                    fmaxf(cr[4 * q + 3] + bs[4 * q + 3], 0.f));
        }
    }
}

// ---------------------------------------------------------------------------
extern "C" void kernel_launch(void* const* d_in, const int* in_sizes, int n_in,
                              void* d_out, int out_size)
{
    const float* af      = (const float*)d_in[0];
    const float* fin     = (const float*)d_in[1];
    const int*   a2b     = (const int*)d_in[2];
    const int*   mapping = (const int*)d_in[3];
    const int*   ml      = (const int*)d_in[5];
    const float* Wi      = (const float*)d_in[6];
    const float* Wh      = (const float*)d_in[7];
    const float* Wo      = (const float*)d_in[8];
    const float* bo      = (const float*)d_in[9];
    float* out = (float*)d_out;
    float* maskbase = out + (size_t)out_size - (size_t)Bm * Am;

    cudaFuncSetAttribute(k_wi,   cudaFuncAttributeMaxDynamicSharedMemorySize, WI_SMB);
    cudaFuncSetAttribute(k_fuse, cudaFuncAttributeMaxDynamicSharedMemorySize, F_SMB);

    k_scan<<<1, 512>>>(ml, maskbase);
    k_tw<<<(128 * (KWI + 128 + KWO) + 255) / 256, 256>>>(Wi, Wh, Wo);
    k_wi<<<1024, 256, WI_SMB>>>(fin);
    k_fuse<<<512, 256, F_SMB>>>(mapping, a2b, af, bo, ml, out);
}

// round 16
// speedup vs baseline: 1.5702x; 1.5702x over previous
#include <cuda_runtime.h>
#include <cuda_bf16.h>
#include <mma.h>
#include <cstdint>

using namespace nvcuda;

#define Bm 512
#define Em 256
#define Am 128
#define Km 6
#define Fm 147
#define AFm 133
#define Hm 128

#define KWI 160
#define KWO 288          // 133 af + 11 zero + 128 m2a + 16 zero (9 chunks of 32)
#define LDA_WI 168
#define LDT 40           // fused-kernel A/B tile stride (bf16, mult of 8)

// f32 scratch
__device__ float g_inp [Bm * Em * Hm];
__device__ int   g_off[Bm];
// pre-split hi/lo bf16 weights, row-major [128][K]
__device__ __align__(16) __nv_bfloat16 g_WiH[128 * KWI];
__device__ __align__(16) __nv_bfloat16 g_WiL[128 * KWI];
__device__ __align__(16) __nv_bfloat16 g_WhH[128 * 128];
__device__ __align__(16) __nv_bfloat16 g_WhL[128 * 128];
__device__ __align__(16) __nv_bfloat16 g_WoH[128 * KWO];
__device__ __align__(16) __nv_bfloat16 g_WoL[128 * KWO];

typedef wmma::fragment<wmma::matrix_a, 16, 16, 16, __nv_bfloat16, wmma::row_major> FragA;
typedef wmma::fragment<wmma::matrix_b, 16, 16, 16, __nv_bfloat16, wmma::col_major> FragB;
typedef wmma::fragment<wmma::accumulator, 16, 16, 16, float> FragC;

// single shared symbol for all kernels
extern __shared__ char smdyn[];

// pack 4 floats into hi-uint2 / lo-uint2
__device__ __forceinline__ void pack4(const float* v, uint2& hp, uint2& lp) {
    __nv_bfloat16 h0 = __float2bfloat16_rn(v[0]), h1 = __float2bfloat16_rn(v[1]),
                  h2 = __float2bfloat16_rn(v[2]), h3 = __float2bfloat16_rn(v[3]);
    hp.x = (uint32_t)__bfloat16_as_ushort(h0) | ((uint32_t)__bfloat16_as_ushort(h1) << 16);
    hp.y = (uint32_t)__bfloat16_as_ushort(h2) | ((uint32_t)__bfloat16_as_ushort(h3) << 16);
    __nv_bfloat16 l0 = __float2bfloat16_rn(v[0] - __bfloat162float(h0));
    __nv_bfloat16 l1 = __float2bfloat16_rn(v[1] - __bfloat162float(h1));
    __nv_bfloat16 l2 = __float2bfloat16_rn(v[2] - __bfloat162float(h2));
    __nv_bfloat16 l3 = __float2bfloat16_rn(v[3] - __bfloat162float(h3));
    lp.x = (uint32_t)__bfloat16_as_ushort(l0) | ((uint32_t)__bfloat16_as_ushort(l1) << 16);
    lp.y = (uint32_t)__bfloat16_as_ushort(l2) | ((uint32_t)__bfloat16_as_ushort(l3) << 16);
}
__device__ __forceinline__ void wr4(__nv_bfloat16* AH, __nv_bfloat16* AL,
                                    int ldm, int r, int c, float4 v) {
    int o = r * ldm + c;
    float vv[4] = {v.x, v.y, v.z, v.w};
    uint2 hp, lp;
    pack4(vv, hp, lp);
    *(uint2*)(AH + o) = hp;
    *(uint2*)(AL + o) = lp;
}

// ---------------------------------------------------------------------------
extern "C" __global__ void __launch_bounds__(512) k_scan(const int* __restrict__ ml,
                                                         float* __restrict__ maskbase)
{
    __shared__ int s[512];
    int t = threadIdx.x;
    int v = ml[t];
    s[t] = v;
    __syncthreads();
    for (int off = 1; off < 512; off <<= 1) {
        int u = (t >= off) ? s[t - off] : 0;
        __syncthreads();
        s[t] += u;
        __syncthreads();
    }
    g_off[t] = s[t] - v;
    for (int i = t; i < Bm * Am; i += 512) {
        int b = i >> 7, a = i & 127;
        maskbase[i] = (a < ml[b]) ? 1.0f : 0.0f;
    }
}

// ---------------------------------------------------------------------------
extern "C" __global__ void __launch_bounds__(256) k_tw(const float* __restrict__ Wi,
                                                       const float* __restrict__ Wh,
                                                       const float* __restrict__ Wo)
{
    int idx = blockIdx.x * 256 + threadIdx.x;
    float v; __nv_bfloat16 *ph, *pl; int o;
    if (idx < 128 * KWI) {
        int n = idx / KWI, k = idx - n * KWI;
        v = (k < Fm) ? Wi[n * Fm + k] : 0.f;
        ph = g_WiH; pl = g_WiL; o = idx;
    } else if (idx < 128 * KWI + 128 * 128) {
        int p = idx - 128 * KWI;
        v = Wh[p];
        ph = g_WhH; pl = g_WhL; o = p;
    } else if (idx < 128 * (KWI + 128 + KWO)) {
        int p = idx - 128 * KWI - 128 * 128;
        int n = p / KWO, k = p - n * KWO;
        if (k < AFm)                     v = Wo[n * 261 + k];
        else if (k >= 144 && k < 272)    v = Wo[n * 261 + k - 11];
        else                             v = 0.f;
        ph = g_WoH; pl = g_WoL; o = p;
    } else return;
    __nv_bfloat16 h = __float2bfloat16_rn(v);
    ph[o] = h;
    pl[o] = __float2bfloat16_rn(v - __bfloat162float(h));
}

// ---------------------------------------------------------------------------
// k_wi: inp = fin @ Wi^T (writes g_inp only; relu happens in k_fuse load)
// ---------------------------------------------------------------------------
#define WI_AH 0
#define WI_AL (128 * LDA_WI)
#define WI_BH (2 * 128 * LDA_WI)
#define WI_BL (3 * 128 * LDA_WI)
#define WI_SMB (4 * 128 * LDA_WI * 2)
#define LD_128 136

extern "C" __global__ void __launch_bounds__(256) k_wi(const float* __restrict__ fin)
{
    __nv_bfloat16* sm = (__nv_bfloat16*)smdyn;
    int tid = threadIdx.x, w = tid >> 5;
    int row0 = blockIdx.x * 128;

    {
        const uint4* sh = (const uint4*)g_WiH;
        const uint4* sl = (const uint4*)g_WiL;
        for (int i = tid; i < 128 * KWI / 8; i += 256) {
            int r = i / (KWI / 8), ch = i - r * (KWI / 8);
            *(uint4*)(sm + WI_BH + r * LDA_WI + ch * 8) = sh[i];
            *(uint4*)(sm + WI_BL + r * LDA_WI + ch * 8) = sl[i];
        }
    }
    {
        int r = tid >> 1, h = tid & 1;
        const float* fr = fin + (size_t)(row0 + r) * Fm;
        for (int c = h * 80; c < h * 80 + 80; c += 4) {
            float4 v;
            v.x = (c + 0 < Fm) ? fr[c + 0] : 0.f;
            v.y = (c + 1 < Fm) ? fr[c + 1] : 0.f;
            v.z = (c + 2 < Fm) ? fr[c + 2] : 0.f;
            v.w = (c + 3 < Fm) ? fr[c + 3] : 0.f;
            wr4(sm + WI_AH, sm + WI_AL, LDA_WI, r, c, v);
        }
    }
    __syncthreads();

    FragC c[8];
#pragma unroll
    for (int nt = 0; nt < 8; nt++) wmma::fill_fragment(c[nt], 0.f);
    for (int ks = 0; ks < KWI / 16; ks++) {
        FragA ah, al;
        wmma::load_matrix_sync(ah, sm + WI_AH + w * 16 * LDA_WI + ks * 16, LDA_WI);
        wmma::load_matrix_sync(al, sm + WI_AL + w * 16 * LDA_WI + ks * 16, LDA_WI);
#pragma unroll
        for (int nt = 0; nt < 8; nt++) {
            FragB bh, bl;
            wmma::load_matrix_sync(bh, sm + WI_BH + nt * 16 * LDA_WI + ks * 16, LDA_WI);
            wmma::load_matrix_sync(bl, sm + WI_BL + nt * 16 * LDA_WI + ks * 16, LDA_WI);
            wmma::mma_sync(c[nt], ah, bh, c[nt]);
            wmma::mma_sync(c[nt], ah, bl, c[nt]);
            wmma::mma_sync(c[nt], al, bh, c[nt]);
        }
    }

    // fragment epilogue: inp = C (no smem round-trip)
#pragma unroll
    for (int nt = 0; nt < 8; nt++) {
        size_t off = (size_t)(row0 + w * 16) * Hm + nt * 16;
        wmma::store_matrix_sync(g_inp + off, c[nt], Hm, wmma::mem_row_major);
    }
}

// ---------------------------------------------------------------------------
// k_fuse: per-molecule block. msg = raw f32 in smem, pair-swizzled:
// pair(r, p) (cols 2p, 2p+1) at msgF2[r*64 + (p ^ (r&15))]
// 2x MP iterations + output GEMM + scatter, fused.
// ---------------------------------------------------------------------------
#define F_MSG 0
#define F_AH  131072
#define F_AL  (F_AH + 256 * LDT * 2)      // 151552
#define F_BH  (F_AL + 256 * LDT * 2)      // 172032
#define F_BL  (F_BH + 128 * LDT * 2)      // 182272
#define F_BIAS (F_BL + 128 * LDT * 2)     // 192512
#define F_SMB (F_BIAS + 512)              // 193024

extern "C" __global__ void __launch_bounds__(256, 1) k_fuse(const int* __restrict__ mapping,
                                                            const int* __restrict__ a2b,
                                                            const float* __restrict__ af,
                                                            const float* __restrict__ bo,
                                                            const int* __restrict__ ml,
                                                            float* __restrict__ out)
{
    float2* msgF2 = (float2*)(smdyn + F_MSG);          // 64 pairs per row
    float*  msgF  = (float*)(smdyn + F_MSG);           // linear alias (epilogue)
    __nv_bfloat16* AHp = (__nv_bfloat16*)(smdyn + F_AH);
    __nv_bfloat16* ALp = (__nv_bfloat16*)(smdyn + F_AL);
    __nv_bfloat16* BHp = (__nv_bfloat16*)(smdyn + F_BH);
    __nv_bfloat16* BLp = (__nv_bfloat16*)(smdyn + F_BL);
    float* biasF = (float*)(smdyn + F_BIAS);

    int tid = threadIdx.x, w = tid >> 5;
    int b = blockIdx.x;

    if (tid < 128) biasF[tid] = bo[tid];

    // per-thread bond mapping (row = tid)
    int map6[6];
    {
        const int* mp = mapping + ((size_t)b * Em + tid) * Km;
#pragma unroll
        for (int s = 0; s < 6; s++) map6[s] = mp[s];
    }

    // ---- msg0 = relu(inp) -> swizzled f32 smem ----
    {
        const float2* src = (const float2*)(g_inp + (size_t)b * Em * Hm);
        for (int i = tid; i < Em * 64; i += 256) {
            int r = i >> 6, p = i & 63;
            float2 v = src[i];
            v.x = fmaxf(v.x, 0.f);
            v.y = fmaxf(v.y, 0.f);
            msgF2[r * 64 + (p ^ (r & 15))] = v;
        }
    }

    // ================= message-passing iterations =================
    for (int iter = 0; iter < 2; iter++) {
        FragC c[2][8];
#pragma unroll
        for (int mt = 0; mt < 2; mt++)
#pragma unroll
            for (int nt = 0; nt < 8; nt++) wmma::fill_fragment(c[mt][nt], 0.f);

        for (int kc = 0; kc < 4; kc++) {
            __syncthreads();   // prev MMA (or init) done before overwrite
            // stage Wh chunk [128][32] hi/lo
            {
                int n = tid >> 1, hf = tid & 1;
                const uint4* sh = (const uint4*)(g_WhH + n * 128 + kc * 32 + hf * 16);
                const uint4* sl = (const uint4*)(g_WhL + n * 128 + kc * 32 + hf * 16);
                uint4* dh = (uint4*)(BHp + n * LDT + hf * 16);
                uint4* dl = (uint4*)(BLp + n * LDT + hf * 16);
                dh[0] = sh[0]; dh[1] = sh[1];
                dl[0] = sl[0]; dl[1] = sl[1];
            }
            // build A chunk: row = tid, cols kc*32..+32 (gather-sum 6, pure f32)
            {
                int r = tid;
#pragma unroll
                for (int g = 0; g < 4; g++) {           // 8 cols per group
                    float acc[8] = {0.f, 0.f, 0.f, 0.f, 0.f, 0.f, 0.f, 0.f};
                    int pbase = kc * 16 + g * 4;
#pragma unroll
                    for (int s = 0; s < 6; s++) {
                        const float2* mrow = msgF2 + map6[s] * 64;
                        int x = map6[s] & 15;
#pragma unroll
                        for (int q = 0; q < 4; q++) {
                            float2 v = mrow[(pbase + q) ^ x];
                            acc[2 * q]     += v.x;
                            acc[2 * q + 1] += v.y;
                        }
                    }
                    uint2 h0, l0, h1, l1;
                    pack4(acc, h0, l0);
                    pack4(acc + 4, h1, l1);
                    *(uint4*)(AHp + r * LDT + g * 8) = make_uint4(h0.x, h0.y, h1.x, h1.y);
                    *(uint4*)(ALp + r * LDT + g * 8) = make_uint4(l0.x, l0.y, l1.x, l1.y);
                }
            }
            __syncthreads();
            // MMA: warp rows [w*32, +32), N=128  (per-mt frags: low reg pressure)
#pragma unroll
            for (int ki = 0; ki < 2; ki++)
#pragma unroll
                for (int mt = 0; mt < 2; mt++) {
                    FragA ah, al;
                    wmma::load_matrix_sync(ah, AHp + (w * 32 + mt * 16) * LDT + ki * 16, LDT);
                    wmma::load_matrix_sync(al, ALp + (w * 32 + mt * 16) * LDT + ki * 16, LDT);
#pragma unroll
                    for (int nt = 0; nt < 8; nt++) {
                        FragB bh, bl;
                        wmma::load_matrix_sync(bh, BHp + nt * 16 * LDT + ki * 16, LDT);
                        wmma::load_matrix_sync(bl, BLp + nt * 16 * LDT + ki * 16, LDT);
                        wmma::mma_sync(c[mt][nt], ah, bh, c[mt][nt]);
                        wmma::mma_sync(c[mt][nt], ah, bl, c[mt][nt]);
                        wmma::mma_sync(c[mt][nt], al, bh, c[mt][nt]);
                    }
                }
        }
        // epilogue: msg = relu(inp + C), written back swizzled (row-local perm)
        __syncthreads();
#pragma unroll
        for (int mt = 0; mt < 2; mt++)
#pragma unroll
            for (int nt = 0; nt < 8; nt++)
                wmma::store_matrix_sync(msgF + (w * 32 + mt * 16) * 128 + nt * 16,
                                        c[mt][nt], 128, wmma::mem_row_major);
        __syncthreads();
        {
            int r = tid, x = r & 15;
            const float4* gi = (const float4*)(g_inp + ((size_t)b * Em + r) * 128);
            float* mf = msgF + r * 128;
            float2* mrow = msgF2 + r * 64;
#pragma unroll
            for (int g = 0; g < 4; g++) {      // 32-col group, swizzle-closed
                float v[32];
#pragma unroll
                for (int q = 0; q < 8; q++) {
                    float4 cv = *(const float4*)(mf + g * 32 + q * 4);
                    float4 iv = gi[g * 8 + q];
                    v[4 * q]     = fmaxf(cv.x + iv.x, 0.f);
                    v[4 * q + 1] = fmaxf(cv.y + iv.y, 0.f);
                    v[4 * q + 2] = fmaxf(cv.z + iv.z, 0.f);
                    v[4 * q + 3] = fmaxf(cv.w + iv.w, 0.f);
                }
#pragma unroll
                for (int q = 0; q < 16; q++) {
                    int p = g * 16 + q;
                    mrow[p ^ x] = make_float2(v[2 * q], v[2 * q + 1]);
                }
            }
        }
    }

    // ================= output GEMM (atoms) =================
    int a = tid >> 1, half = tid & 1;
    int g6[6];
    {
        const int* gp = a2b + ((size_t)b * Am + a) * Km;
#pragma unroll
        for (int s = 0; s < 6; s++) g6[s] = gp[s];
    }

    FragC co[8];
#pragma unroll
    for (int nt = 0; nt < 8; nt++) wmma::fill_fragment(co[nt], 0.f);

    const float* afrow = af + ((size_t)b * Am + a) * AFm;
    for (int kc = 0; kc < 9; kc++) {
        __syncthreads();
        // stage Wo chunk
        {
            int n = tid >> 1, hf = tid & 1;
            const uint4* sh = (const uint4*)(g_WoH + n * KWO + kc * 32 + hf * 16);
            const uint4* sl = (const uint4*)(g_WoL + n * KWO + kc * 32 + hf * 16);
            uint4* dh = (uint4*)(BHp + n * LDT + hf * 16);
            uint4* dl = (uint4*)(BLp + n * LDT + hf * 16);
            dh[0] = sh[0]; dh[1] = sh[1];
            dl[0] = sl[0]; dl[1] = sl[1];
        }
        // build A-cat chunk rows 0..127 (2 threads/row, 16 cols each)
        {
            int k0 = kc * 32 + half * 16;
            float vv[16];
            if (k0 + 16 <= AFm) {
#pragma unroll
                for (int j = 0; j < 16; j++) vv[j] = afrow[k0 + j];
            } else if (k0 == 128) {
#pragma unroll
                for (int j = 0; j < 16; j++) vv[j] = (128 + j < AFm) ? afrow[128 + j] : 0.f;
            } else if (k0 >= 144 && k0 < 272) {
#pragma unroll
                for (int j = 0; j < 16; j++) vv[j] = 0.f;
                int p0 = (k0 - 144) >> 1;
#pragma unroll
                for (int s = 0; s < 6; s++) {
                    const float2* mrow = msgF2 + g6[s] * 64;
                    int x = g6[s] & 15;
#pragma unroll
                    for (int q = 0; q < 8; q++) {
                        float2 v = mrow[(p0 + q) ^ x];
                        vv[2 * q]     += v.x;
                        vv[2 * q + 1] += v.y;
                    }
                }
            } else {
#pragma unroll
                for (int j = 0; j < 16; j++) vv[j] = 0.f;
            }
            uint2 h0, l0, h1, l1, h2, l2, h3, l3;
            pack4(vv, h0, l0); pack4(vv + 4, h1, l1);
            pack4(vv + 8, h2, l2); pack4(vv + 12, h3, l3);
            uint4* dh = (uint4*)(AHp + a * LDT + half * 16);
            uint4* dl = (uint4*)(ALp + a * LDT + half * 16);
            dh[0] = make_uint4(h0.x, h0.y, h1.x, h1.y);
            dh[1] = make_uint4(h2.x, h2.y, h3.x, h3.y);
            dl[0] = make_uint4(l0.x, l0.y, l1.x, l1.y);
            dl[1] = make_uint4(l2.x, l2.y, l3.x, l3.y);
        }
        __syncthreads();
        // MMA: warp rows [w*16, +16)
#pragma unroll
        for (int ki = 0; ki < 2; ki++) {
            FragA ah, al;
            wmma::load_matrix_sync(ah, AHp + w * 16 * LDT + ki * 16, LDT);
            wmma::load_matrix_sync(al, ALp + w * 16 * LDT + ki * 16, LDT);
#pragma unroll
            for (int nt = 0; nt < 8; nt++) {
                FragB bh, bl;
                wmma::load_matrix_sync(bh, BHp + nt * 16 * LDT + ki * 16, LDT);
                wmma::load_matrix_sync(bl, BLp + nt * 16 * LDT + ki * 16, LDT);
                wmma::mma_sync(co[nt], ah, bh, co[nt]);
                wmma::mma_sync(co[nt], ah, bl, co[nt]);
                wmma::mma_sync(co[nt], al, bh, co[nt]);
            }
        }
    }
    __syncthreads();
#pragma unroll
    for (int nt = 0; nt < 8; nt++)
        wmma::store_matrix_sync(msgF + w * 16 * 128 + nt * 16, co[nt], 128, wmma::mem_row_major);
    __syncthreads();

    // bias + relu + scatter (2 threads/row)
    {
        int len = ml[b];
        if (a < len) {
            const float* cr = msgF + a * 128 + half * 64;
            const float* bs = biasF + half * 64;
            float4* po = (float4*)(out + (size_t)(g_off[b] + a) * Hm + half * 64);
#pragma unroll
            for (int q = 0; q < 16; q++)
                po[q] = make_float4(fmaxf(cr[4 * q + 0] + bs[4 * q + 0], 0.f),
                                    fmaxf(cr[4 * q + 1] + bs[4 * q + 1], 0.f),
                                    fmaxf(cr[4 * q + 2] + bs[4 * q + 2], 0.f),
                                    fmaxf(cr[4 * q + 3] + bs[4 * q + 3], 0.f));
        }
    }
}

// ---------------------------------------------------------------------------
extern "C" void kernel_launch(void* const* d_in, const int* in_sizes, int n_in,
                              void* d_out, int out_size)
{
    const float* af      = (const float*)d_in[0];
    const float* fin     = (const float*)d_in[1];
    const int*   a2b     = (const int*)d_in[2];
    const int*   mapping = (const int*)d_in[3];
    const int*   ml      = (const int*)d_in[5];
    const float* Wi      = (const float*)d_in[6];
    const float* Wh      = (const float*)d_in[7];
    const float* Wo      = (const float*)d_in[8];
    const float* bo      = (const float*)d_in[9];
    float* out = (float*)d_out;
    float* maskbase = out + (size_t)out_size - (size_t)Bm * Am;

    cudaFuncSetAttribute(k_wi,   cudaFuncAttributeMaxDynamicSharedMemorySize, WI_SMB);
    cudaFuncSetAttribute(k_fuse, cudaFuncAttributeMaxDynamicSharedMemorySize, F_SMB);

    k_scan<<<1, 512>>>(ml, maskbase);
    k_tw<<<(128 * (KWI + 128 + KWO) + 255) / 256, 256>>>(Wi, Wh, Wo);
    k_wi<<<1024, 256, WI_SMB>>>(fin);
    k_fuse<<<512, 256, F_SMB>>>(mapping, a2b, af, bo, ml, out);
}

// round 17
// speedup vs baseline: 1.6761x; 1.0674x over previous
#include <cuda_runtime.h>
#include <cuda_bf16.h>
#include <mma.h>
#include <cstdint>

using namespace nvcuda;

#define Bm 512
#define Em 256
#define Am 128
#define Km 6
#define Fm 147
#define AFm 133
#define Hm 128

#define KWI 160
#define KWO 288          // 133 af + 11 zero + 128 m2a + 16 zero (9 chunks of 32)
#define LDA_WI 168
#define LDT 40           // fused-kernel A/B tile stride (bf16, mult of 8)

// f32 scratch
__device__ float g_inp [Bm * Em * Hm];
__device__ int   g_off[Bm];
// pre-split hi/lo bf16 weights, row-major [128][K]
__device__ __align__(16) __nv_bfloat16 g_WiH[128 * KWI];
__device__ __align__(16) __nv_bfloat16 g_WiL[128 * KWI];
__device__ __align__(16) __nv_bfloat16 g_WhH[128 * 128];
__device__ __align__(16) __nv_bfloat16 g_WhL[128 * 128];
__device__ __align__(16) __nv_bfloat16 g_WoH[128 * KWO];
__device__ __align__(16) __nv_bfloat16 g_WoL[128 * KWO];

typedef wmma::fragment<wmma::matrix_a, 16, 16, 16, __nv_bfloat16, wmma::row_major> FragA;
typedef wmma::fragment<wmma::matrix_b, 16, 16, 16, __nv_bfloat16, wmma::col_major> FragB;
typedef wmma::fragment<wmma::accumulator, 16, 16, 16, float> FragC;

extern __shared__ char smdyn[];

// pack 4 floats into hi-uint2 / lo-uint2
__device__ __forceinline__ void pack4(const float* v, uint2& hp, uint2& lp) {
    __nv_bfloat16 h0 = __float2bfloat16_rn(v[0]), h1 = __float2bfloat16_rn(v[1]),
                  h2 = __float2bfloat16_rn(v[2]), h3 = __float2bfloat16_rn(v[3]);
    hp.x = (uint32_t)__bfloat16_as_ushort(h0) | ((uint32_t)__bfloat16_as_ushort(h1) << 16);
    hp.y = (uint32_t)__bfloat16_as_ushort(h2) | ((uint32_t)__bfloat16_as_ushort(h3) << 16);
    __nv_bfloat16 l0 = __float2bfloat16_rn(v[0] - __bfloat162float(h0));
    __nv_bfloat16 l1 = __float2bfloat16_rn(v[1] - __bfloat162float(h1));
    __nv_bfloat16 l2 = __float2bfloat16_rn(v[2] - __bfloat162float(h2));
    __nv_bfloat16 l3 = __float2bfloat16_rn(v[3] - __bfloat162float(h3));
    lp.x = (uint32_t)__bfloat16_as_ushort(l0) | ((uint32_t)__bfloat16_as_ushort(l1) << 16);
    lp.y = (uint32_t)__bfloat16_as_ushort(l2) | ((uint32_t)__bfloat16_as_ushort(l3) << 16);
}
__device__ __forceinline__ void wr4(__nv_bfloat16* AH, __nv_bfloat16* AL,
                                    int ldm, int r, int c, float4 v) {
    int o = r * ldm + c;
    float vv[4] = {v.x, v.y, v.z, v.w};
    uint2 hp, lp;
    pack4(vv, hp, lp);
    *(uint2*)(AH + o) = hp;
    *(uint2*)(AL + o) = lp;
}

// ---------------------------------------------------------------------------
extern "C" __global__ void __launch_bounds__(512) k_scan(const int* __restrict__ ml,
                                                         float* __restrict__ maskbase)
{
    __shared__ int s[512];
    int t = threadIdx.x;
    int v = ml[t];
    s[t] = v;
    __syncthreads();
    for (int off = 1; off < 512; off <<= 1) {
        int u = (t >= off) ? s[t - off] : 0;
        __syncthreads();
        s[t] += u;
        __syncthreads();
    }
    g_off[t] = s[t] - v;
    for (int i = t; i < Bm * Am; i += 512) {
        int b = i >> 7, a = i & 127;
        maskbase[i] = (a < ml[b]) ? 1.0f : 0.0f;
    }
}

// ---------------------------------------------------------------------------
extern "C" __global__ void __launch_bounds__(256) k_tw(const float* __restrict__ Wi,
                                                       const float* __restrict__ Wh,
                                                       const float* __restrict__ Wo)
{
    int idx = blockIdx.x * 256 + threadIdx.x;
    float v; __nv_bfloat16 *ph, *pl; int o;
    if (idx < 128 * KWI) {
        int n = idx / KWI, k = idx - n * KWI;
        v = (k < Fm) ? Wi[n * Fm + k] : 0.f;
        ph = g_WiH; pl = g_WiL; o = idx;
    } else if (idx < 128 * KWI + 128 * 128) {
        int p = idx - 128 * KWI;
        v = Wh[p];
        ph = g_WhH; pl = g_WhL; o = p;
    } else if (idx < 128 * (KWI + 128 + KWO)) {
        int p = idx - 128 * KWI - 128 * 128;
        int n = p / KWO, k = p - n * KWO;
        if (k < AFm)                     v = Wo[n * 261 + k];
        else if (k >= 144 && k < 272)    v = Wo[n * 261 + k - 11];
        else                             v = 0.f;
        ph = g_WoH; pl = g_WoL; o = p;
    } else return;
    __nv_bfloat16 h = __float2bfloat16_rn(v);
    ph[o] = h;
    pl[o] = __float2bfloat16_rn(v - __bfloat162float(h));
}

// ---------------------------------------------------------------------------
// k_wi (proven): inp = fin @ Wi^T (fragment epilogue, g_inp only)
// ---------------------------------------------------------------------------
#define WI_AH 0
#define WI_AL (128 * LDA_WI)
#define WI_BH (2 * 128 * LDA_WI)
#define WI_BL (3 * 128 * LDA_WI)
#define WI_SMB (4 * 128 * LDA_WI * 2)

extern "C" __global__ void __launch_bounds__(256) k_wi(const float* __restrict__ fin)
{
    __nv_bfloat16* sm = (__nv_bfloat16*)smdyn;
    int tid = threadIdx.x, w = tid >> 5;
    int row0 = blockIdx.x * 128;

    {
        const uint4* sh = (const uint4*)g_WiH;
        const uint4* sl = (const uint4*)g_WiL;
        for (int i = tid; i < 128 * KWI / 8; i += 256) {
            int r = i / (KWI / 8), ch = i - r * (KWI / 8);
            *(uint4*)(sm + WI_BH + r * LDA_WI + ch * 8) = sh[i];
            *(uint4*)(sm + WI_BL + r * LDA_WI + ch * 8) = sl[i];
        }
    }
    {
        int r = tid >> 1, h = tid & 1;
        const float* fr = fin + (size_t)(row0 + r) * Fm;
        for (int c = h * 80; c < h * 80 + 80; c += 4) {
            float4 v;
            v.x = (c + 0 < Fm) ? fr[c + 0] : 0.f;
            v.y = (c + 1 < Fm) ? fr[c + 1] : 0.f;
            v.z = (c + 2 < Fm) ? fr[c + 2] : 0.f;
            v.w = (c + 3 < Fm) ? fr[c + 3] : 0.f;
            wr4(sm + WI_AH, sm + WI_AL, LDA_WI, r, c, v);
        }
    }
    __syncthreads();

    FragC c[8];
#pragma unroll
    for (int nt = 0; nt < 8; nt++) wmma::fill_fragment(c[nt], 0.f);
    for (int ks = 0; ks < KWI / 16; ks++) {
        FragA ah, al;
        wmma::load_matrix_sync(ah, sm + WI_AH + w * 16 * LDA_WI + ks * 16, LDA_WI);
        wmma::load_matrix_sync(al, sm + WI_AL + w * 16 * LDA_WI + ks * 16, LDA_WI);
#pragma unroll
        for (int nt = 0; nt < 8; nt++) {
            FragB bh, bl;
            wmma::load_matrix_sync(bh, sm + WI_BH + nt * 16 * LDA_WI + ks * 16, LDA_WI);
            wmma::load_matrix_sync(bl, sm + WI_BL + nt * 16 * LDA_WI + ks * 16, LDA_WI);
            wmma::mma_sync(c[nt], ah, bh, c[nt]);
            wmma::mma_sync(c[nt], ah, bl, c[nt]);
            wmma::mma_sync(c[nt], al, bh, c[nt]);
        }
    }
#pragma unroll
    for (int nt = 0; nt < 8; nt++) {
        size_t off = (size_t)(row0 + w * 16) * Hm + nt * 16;
        wmma::store_matrix_sync(g_inp + off, c[nt], Hm, wmma::mem_row_major);
    }
}

// ---------------------------------------------------------------------------
// k_fuse: per-molecule block, 512 threads (16 warps).
// msg raw f32 pair-swizzled: pair(r,p) at msgF2[r*64 + (p ^ (r&15))]
// ---------------------------------------------------------------------------
#define F_MSG 0
#define F_AH  131072
#define F_AL  (F_AH + 256 * LDT * 2)
#define F_BH  (F_AL + 256 * LDT * 2)
#define F_BL  (F_BH + 128 * LDT * 2)
#define F_BIAS (F_BL + 128 * LDT * 2)
#define F_SMB (F_BIAS + 512)

extern "C" __global__ void __launch_bounds__(512, 1) k_fuse(const int* __restrict__ mapping,
                                                            const int* __restrict__ a2b,
                                                            const float* __restrict__ af,
                                                            const float* __restrict__ bo,
                                                            const int* __restrict__ ml,
                                                            float* __restrict__ out)
{
    float2* msgF2 = (float2*)(smdyn + F_MSG);
    float*  msgF  = (float*)(smdyn + F_MSG);
    __nv_bfloat16* AHp = (__nv_bfloat16*)(smdyn + F_AH);
    __nv_bfloat16* ALp = (__nv_bfloat16*)(smdyn + F_AL);
    __nv_bfloat16* BHp = (__nv_bfloat16*)(smdyn + F_BH);
    __nv_bfloat16* BLp = (__nv_bfloat16*)(smdyn + F_BL);
    float* biasF = (float*)(smdyn + F_BIAS);

    int tid = threadIdx.x, w = tid >> 5;
    int b = blockIdx.x;

    if (tid < 128) biasF[tid] = bo[tid];

    int rh = tid >> 1, half = tid & 1;       // 2 threads per bond row
    int map6[6];
    {
        const int* mp = mapping + ((size_t)b * Em + rh) * Km;
#pragma unroll
        for (int s = 0; s < 6; s++) map6[s] = mp[s];
    }

    // msg0 = relu(inp) -> swizzled f32 smem
    {
        const float2* src = (const float2*)(g_inp + (size_t)b * Em * Hm);
        for (int i = tid; i < Em * 64; i += 512) {
            int r = i >> 6, p = i & 63;
            float2 v = src[i];
            v.x = fmaxf(v.x, 0.f);
            v.y = fmaxf(v.y, 0.f);
            msgF2[r * 64 + (p ^ (r & 15))] = v;
        }
    }

    // ================= message-passing iterations =================
    for (int iter = 0; iter < 2; iter++) {
        FragC c[8];                      // warp w: rows [w*16,+16) x N=128
#pragma unroll
        for (int nt = 0; nt < 8; nt++) wmma::fill_fragment(c[nt], 0.f);

        for (int kc = 0; kc < 4; kc++) {
            __syncthreads();
            // stage Wh chunk [128][32] hi/lo (4 threads/row)
            {
                int n = tid >> 2, hf = tid & 3;
                *(uint4*)(BHp + n * LDT + hf * 8) = *(const uint4*)(g_WhH + n * 128 + kc * 32 + hf * 8);
                *(uint4*)(BLp + n * LDT + hf * 8) = *(const uint4*)(g_WhL + n * 128 + kc * 32 + hf * 8);
            }
            // build A chunk: 2 threads/row, 16 cols each (2 groups of 8)
            {
#pragma unroll
                for (int gg = 0; gg < 2; gg++) {
                    int g = 2 * half + gg;
                    float acc[8] = {0.f, 0.f, 0.f, 0.f, 0.f, 0.f, 0.f, 0.f};
                    int pbase = kc * 16 + g * 4;
#pragma unroll
                    for (int s = 0; s < 6; s++) {
                        const float2* mrow = msgF2 + map6[s] * 64;
                        int x = map6[s] & 15;
#pragma unroll
                        for (int q = 0; q < 4; q++) {
                            float2 v = mrow[(pbase + q) ^ x];
                            acc[2 * q]     += v.x;
                            acc[2 * q + 1] += v.y;
                        }
                    }
                    uint2 h0, l0, h1, l1;
                    pack4(acc, h0, l0);
                    pack4(acc + 4, h1, l1);
                    *(uint4*)(AHp + rh * LDT + g * 8) = make_uint4(h0.x, h0.y, h1.x, h1.y);
                    *(uint4*)(ALp + rh * LDT + g * 8) = make_uint4(l0.x, l0.y, l1.x, l1.y);
                }
            }
            __syncthreads();
            // MMA: warp rows [w*16,+16)
#pragma unroll
            for (int ki = 0; ki < 2; ki++) {
                FragA ah, al;
                wmma::load_matrix_sync(ah, AHp + w * 16 * LDT + ki * 16, LDT);
                wmma::load_matrix_sync(al, ALp + w * 16 * LDT + ki * 16, LDT);
#pragma unroll
                for (int nt = 0; nt < 8; nt++) {
                    FragB bh, bl;
                    wmma::load_matrix_sync(bh, BHp + nt * 16 * LDT + ki * 16, LDT);
                    wmma::load_matrix_sync(bl, BLp + nt * 16 * LDT + ki * 16, LDT);
                    wmma::mma_sync(c[nt], ah, bh, c[nt]);
                    wmma::mma_sync(c[nt], ah, bl, c[nt]);
                    wmma::mma_sync(c[nt], al, bh, c[nt]);
                }
            }
        }
        // epilogue: msg = relu(inp + C)
        __syncthreads();
#pragma unroll
        for (int nt = 0; nt < 8; nt++)
            wmma::store_matrix_sync(msgF + w * 16 * 128 + nt * 16, c[nt], 128, wmma::mem_row_major);
        __syncthreads();
        {
            int r = rh, x = r & 15;
            const float4* gi = (const float4*)(g_inp + ((size_t)b * Em + r) * 128);
            float* mf = msgF + r * 128;
            float2* mrow = msgF2 + r * 64;
#pragma unroll
            for (int gg = 0; gg < 2; gg++) {
                int g = 2 * half + gg;
                float v[32];
#pragma unroll
                for (int q = 0; q < 8; q++) {
                    float4 cv = *(const float4*)(mf + g * 32 + q * 4);
                    float4 iv = gi[g * 8 + q];
                    v[4 * q]     = fmaxf(cv.x + iv.x, 0.f);
                    v[4 * q + 1] = fmaxf(cv.y + iv.y, 0.f);
                    v[4 * q + 2] = fmaxf(cv.z + iv.z, 0.f);
                    v[4 * q + 3] = fmaxf(cv.w + iv.w, 0.f);
                }
#pragma unroll
                for (int q = 0; q < 16; q++) {
                    int p = g * 16 + q;
                    mrow[p ^ x] = make_float2(v[2 * q], v[2 * q + 1]);
                }
            }
        }
    }

    // ================= output GEMM (atoms) =================
    int a = tid >> 2, quarter = tid & 3;     // 4 threads per atom row
    int g6[6];
    {
        const int* gp = a2b + ((size_t)b * Am + a) * Km;
#pragma unroll
        for (int s = 0; s < 6; s++) g6[s] = gp[s];
    }

    int mtile = w >> 1, n0 = (w & 1) * 64;   // warp: rows [mtile*16,+16) x cols [n0,+64)
    FragC co[4];
#pragma unroll
    for (int nt = 0; nt < 4; nt++) wmma::fill_fragment(co[nt], 0.f);

    const float* afrow = af + ((size_t)b * Am + a) * AFm;
    for (int kc = 0; kc < 9; kc++) {
        __syncthreads();
        // stage Wo chunk (4 threads/row)
        {
            int n = tid >> 2, hf = tid & 3;
            *(uint4*)(BHp + n * LDT + hf * 8) = *(const uint4*)(g_WoH + n * KWO + kc * 32 + hf * 8);
            *(uint4*)(BLp + n * LDT + hf * 8) = *(const uint4*)(g_WoL + n * KWO + kc * 32 + hf * 8);
        }
        // build A-cat chunk: 4 threads/row, 8 cols each
        {
            int k0 = kc * 32 + quarter * 8;
            float vv[8];
            if (k0 + 8 <= AFm) {
#pragma unroll
                for (int j = 0; j < 8; j++) vv[j] = afrow[k0 + j];
            } else if (k0 < AFm) {          // group 128..135
#pragma unroll
                for (int j = 0; j < 8; j++) vv[j] = (k0 + j < AFm) ? afrow[k0 + j] : 0.f;
            } else if (k0 >= 144 && k0 < 272) {
                float acc[8] = {0.f, 0.f, 0.f, 0.f, 0.f, 0.f, 0.f, 0.f};
                int p0 = (k0 - 144) >> 1;
#pragma unroll
                for (int s = 0; s < 6; s++) {
                    const float2* mrow = msgF2 + g6[s] * 64;
                    int x = g6[s] & 15;
#pragma unroll
                    for (int q = 0; q < 4; q++) {
                        float2 v = mrow[(p0 + q) ^ x];
                        acc[2 * q]     += v.x;
                        acc[2 * q + 1] += v.y;
                    }
                }
#pragma unroll
                for (int j = 0; j < 8; j++) vv[j] = acc[j];
            } else {
#pragma unroll
                for (int j = 0; j < 8; j++) vv[j] = 0.f;
            }
            uint2 h0, l0, h1, l1;
            pack4(vv, h0, l0);
            pack4(vv + 4, h1, l1);
            *(uint4*)(AHp + a * LDT + quarter * 8) = make_uint4(h0.x, h0.y, h1.x, h1.y);
            *(uint4*)(ALp + a * LDT + quarter * 8) = make_uint4(l0.x, l0.y, l1.x, l1.y);
        }
        __syncthreads();
#pragma unroll
        for (int ki = 0; ki < 2; ki++) {
            FragA ah, al;
            wmma::load_matrix_sync(ah, AHp + mtile * 16 * LDT + ki * 16, LDT);
            wmma::load_matrix_sync(al, ALp + mtile * 16 * LDT + ki * 16, LDT);
#pragma unroll
            for (int nt = 0; nt < 4; nt++) {
                FragB bh, bl;
                wmma::load_matrix_sync(bh, BHp + (n0 + nt * 16) * LDT + ki * 16, LDT);
                wmma::load_matrix_sync(bl, BLp + (n0 + nt * 16) * LDT + ki * 16, LDT);
                wmma::mma_sync(co[nt], ah, bh, co[nt]);
                wmma::mma_sync(co[nt], ah, bl, co[nt]);
                wmma::mma_sync(co[nt], al, bh, co[nt]);
            }
        }
    }
    __syncthreads();
#pragma unroll
    for (int nt = 0; nt < 4; nt++)
        wmma::store_matrix_sync(msgF + mtile * 16 * 128 + n0 + nt * 16, co[nt], 128, wmma::mem_row_major);
    __syncthreads();

    // bias + relu + scatter (4 threads/row, 32 cols each)
    {
        int len = ml[b];
        if (a < len) {
            const float* cr = msgF + a * 128 + quarter * 32;
            const float* bs = biasF + quarter * 32;
            float4* po = (float4*)(out + (size_t)(g_off[b] + a) * Hm + quarter * 32);
#pragma unroll
            for (int q = 0; q < 8; q++)
                po[q] = make_float4(fmaxf(cr[4 * q + 0] + bs[4 * q + 0], 0.f),
                                    fmaxf(cr[4 * q + 1] + bs[4 * q + 1], 0.f),
                                    fmaxf(cr[4 * q + 2] + bs[4 * q + 2], 0.f),
                                    fmaxf(cr[4 * q + 3] + bs[4 * q + 3], 0.f));
        }
    }
}

// ---------------------------------------------------------------------------
extern "C" void kernel_launch(void* const* d_in, const int* in_sizes, int n_in,
                              void* d_out, int out_size)
{
    const float* af      = (const float*)d_in[0];
    const float* fin     = (const float*)d_in[1];
    const int*   a2b     = (const int*)d_in[2];
    const int*   mapping = (const int*)d_in[3];
    const int*   ml      = (const int*)d_in[5];
    const float* Wi      = (const float*)d_in[6];
    const float* Wh      = (const float*)d_in[7];
    const float* Wo      = (const float*)d_in[8];
    const float* bo      = (const float*)d_in[9];
    float* out = (float*)d_out;
    float* maskbase = out + (size_t)out_size - (size_t)Bm * Am;

    cudaFuncSetAttribute(k_wi,   cudaFuncAttributeMaxDynamicSharedMemorySize, WI_SMB);
    cudaFuncSetAttribute(k_fuse, cudaFuncAttributeMaxDynamicSharedMemorySize, F_SMB);

    k_scan<<<1, 512>>>(ml, maskbase);
    k_tw<<<(128 * (KWI + 128 + KWO) + 255) / 256, 256>>>(Wi, Wh, Wo);
    k_wi<<<1024, 256, WI_SMB>>>(fin);
    k_fuse<<<512, 512, F_SMB>>>(mapping, a2b, af, bo, ml, out);
}